// round 1
// baseline (speedup 1.0000x reference)
#include <cuda_runtime.h>
#include <cstdint>

// Problem constants
#define NROWS 65536      // B*H*W = 16*64*64
#define DDIM  128
#define KCODE 4096
#define BM    64         // rows per block
#define BK    64         // codes per tile
#define NTILES (KCODE / BK)
#define HW    4096
#define BATCH 16
#define NELEM (16 * 128 * 64 * 64)   // 8388608

// Scratch (no allocations allowed)
__device__ float  g_enorm[KCODE];
__device__ int    g_idx[NROWS];
__device__ double g_loss;

// ---------------------------------------------------------------------------
// Kernel 0: per-code squared norms + zero the loss accumulator
// ---------------------------------------------------------------------------
__global__ void enorm_kernel(const float* __restrict__ emb) {
    if (blockIdx.x == 0 && threadIdx.x == 0) g_loss = 0.0;
    int warp = (blockIdx.x * blockDim.x + threadIdx.x) >> 5;
    int lane = threadIdx.x & 31;
    int nwarps = (gridDim.x * blockDim.x) >> 5;
    for (int k = warp; k < KCODE; k += nwarps) {
        const float4* row = reinterpret_cast<const float4*>(emb + (size_t)k * DDIM);
        float4 v = row[lane];   // 32 lanes * 4 = 128 dims
        float s = v.x * v.x + v.y * v.y + v.z * v.z + v.w * v.w;
        #pragma unroll
        for (int o = 16; o > 0; o >>= 1) s += __shfl_down_sync(0xffffffffu, s, o);
        if (lane == 0) g_enorm[k] = s;
    }
}

// ---------------------------------------------------------------------------
// Kernel 1: streaming argmin GEMM.
//   score(n,k) = ||e_k||^2 - 2 * z_n . e_k      (||z||^2 constant per row)
//   g_idx[n] = argmin_k score, g_loss += sum_n (||z_n||^2 + min score)
//
// smem layout (dynamic, 73984 B):
//   zs  [128][64]  d-major z tile (transposed once per block)
//   es  [128][64]  d-major e tile, XOR-swizzled columns: p = c ^ ((d>>2 & 15)<<2)
//   z2s [64]       per-row ||z||^2
//   redv[64][16], redi[64][16]  cross-thread min reduction
// ---------------------------------------------------------------------------
#define SMEM_BYTES ((DDIM*BM + DDIM*BK + BM + BM*16) * 4 + BM*16 * 4)

__global__ void __launch_bounds__(256) argmin_kernel(const float* __restrict__ z,
                                                     const float* __restrict__ emb) {
    extern __shared__ float smem[];
    float* zs  = smem;                 // 8192 floats
    float* es  = zs + DDIM * BM;       // 8192 floats
    float* z2s = es + DDIM * BK;       // 64
    float* redv = z2s + BM;            // 1024
    int*   redi = (int*)(redv + BM * 16);

    const int tid = threadIdx.x;
    const int tx = tid & 15;           // code group
    const int ty = tid >> 4;           // row group
    const int row0 = blockIdx.x * BM;

    // ---- load z tile, transpose to d-major (store conflicts irrelevant: once) ----
    const float4* zv = reinterpret_cast<const float4*>(z + (size_t)row0 * DDIM);
    #pragma unroll
    for (int i = 0; i < 8; ++i) {
        int f = i * 256 + tid;
        int r = f >> 5;          // 0..63
        int dc = f & 31;         // float4 chunk along D
        float4 v = zv[r * 32 + dc];
        zs[(dc * 4 + 0) * BM + r] = v.x;
        zs[(dc * 4 + 1) * BM + r] = v.y;
        zs[(dc * 4 + 2) * BM + r] = v.z;
        zs[(dc * 4 + 3) * BM + r] = v.w;
    }
    __syncthreads();

    // per-row ||z||^2 (only needed for the loss)
    if (tid < BM) {
        float s = 0.f;
        #pragma unroll 8
        for (int d = 0; d < DDIM; ++d) { float v = zs[d * BM + tid]; s += v * v; }
        z2s[tid] = s;
    }

    float bestv[4];
    int   besti[4];
    #pragma unroll
    for (int i = 0; i < 4; ++i) { bestv[i] = 3.4e38f; besti[i] = 0; }

    for (int kt = 0; kt < NTILES; ++kt) {
        // ---- load e tile, transpose + swizzle ----
        const float4* ev = reinterpret_cast<const float4*>(emb + (size_t)kt * BK * DDIM);
        #pragma unroll
        for (int i = 0; i < 8; ++i) {
            int f = i * 256 + tid;
            int c = f >> 5;      // code within tile
            int dc = f & 31;
            float4 v = ev[c * 32 + dc];
            int pc = c ^ ((dc & 15) << 2);   // swizzle (pure column permutation per d-group)
            es[(dc * 4 + 0) * BK + pc] = v.x;
            es[(dc * 4 + 1) * BK + pc] = v.y;
            es[(dc * 4 + 2) * BK + pc] = v.z;
            es[(dc * 4 + 3) * BK + pc] = v.w;
        }
        __syncthreads();

        // ---- 4x4 register tile dot products over 128 dims ----
        float acc[4][4];
        #pragma unroll
        for (int i = 0; i < 4; ++i)
            #pragma unroll
            for (int j = 0; j < 4; ++j) acc[i][j] = 0.f;

        #pragma unroll 4
        for (int d4 = 0; d4 < 32; ++d4) {
            // physical column holding logical codes [4*tx .. 4*tx+3] for rows d4*4..d4*4+3
            const int pcol = 4 * (tx ^ (d4 & 15));
            #pragma unroll
            for (int q = 0; q < 4; ++q) {
                const int d = d4 * 4 + q;
                float4 zr = *reinterpret_cast<const float4*>(&zs[d * BM + ty * 4]);
                float4 ec = *reinterpret_cast<const float4*>(&es[d * BK + pcol]);
                acc[0][0] += zr.x * ec.x; acc[0][1] += zr.x * ec.y;
                acc[0][2] += zr.x * ec.z; acc[0][3] += zr.x * ec.w;
                acc[1][0] += zr.y * ec.x; acc[1][1] += zr.y * ec.y;
                acc[1][2] += zr.y * ec.z; acc[1][3] += zr.y * ec.w;
                acc[2][0] += zr.z * ec.x; acc[2][1] += zr.z * ec.y;
                acc[2][2] += zr.z * ec.z; acc[2][3] += zr.z * ec.w;
                acc[3][0] += zr.w * ec.x; acc[3][1] += zr.w * ec.y;
                acc[3][2] += zr.w * ec.z; acc[3][3] += zr.w * ec.w;
            }
        }

        // ---- score + running min (k strictly increasing => '<' matches argmin first-min) ----
        #pragma unroll
        for (int j = 0; j < 4; ++j) {
            int cg = kt * BK + tx * 4 + j;
            float en = __ldg(&g_enorm[cg]);
            #pragma unroll
            for (int i = 0; i < 4; ++i) {
                float sc = fmaf(-2.f, acc[i][j], en);
                if (sc < bestv[i]) { bestv[i] = sc; besti[i] = cg; }
            }
        }
        __syncthreads();   // before overwriting es next tile
    }

    // ---- cross-thread (tx) min reduction per row ----
    #pragma unroll
    for (int i = 0; i < 4; ++i) {
        int r = ty * 4 + i;
        redv[r * 16 + tx] = bestv[i];
        redi[r * 16 + tx] = besti[i];
    }
    __syncthreads();

    if (tid < BM) {
        int r = tid;
        float bv = redv[r * 16];
        int   bi = redi[r * 16];
        #pragma unroll
        for (int t = 1; t < 16; ++t) {
            float v = redv[r * 16 + t];
            int  ii = redi[r * 16 + t];
            if (v < bv || (v == bv && ii < bi)) { bv = v; bi = ii; }
        }
        g_idx[row0 + r] = bi;
        double dd = (double)(z2s[r] + bv);   // ||z - e||^2 for this row
        #pragma unroll
        for (int o = 16; o > 0; o >>= 1)
            dd += __shfl_down_sync(0xffffffffu, dd, o);
        if ((tid & 31) == 0) atomicAdd(&g_loss, dd);
    }
}

// ---------------------------------------------------------------------------
// Kernel 2: gather + transpose to [B, D, H, W]. Coalesced stores along hw.
// ---------------------------------------------------------------------------
__global__ void gather_kernel(const float* __restrict__ emb, float* __restrict__ out) {
    int hw = blockIdx.x * blockDim.x + threadIdx.x;  // 0..4095
    int d  = blockIdx.y;                             // 0..127
    int b  = blockIdx.z;                             // 0..15
    int id = g_idx[b * HW + hw];
    out[((size_t)(b * DDIM + d)) * HW + hw] = __ldg(&emb[(size_t)id * DDIM + d]);
}

// ---------------------------------------------------------------------------
// Kernel 3: scalar loss = 1.25 * mean(||z_q - z||^2)
// ---------------------------------------------------------------------------
__global__ void loss_kernel(float* __restrict__ out) {
    out[NELEM] = (float)(1.25 * g_loss / (double)NELEM);
}

// ---------------------------------------------------------------------------
extern "C" void kernel_launch(void* const* d_in, const int* in_sizes, int n_in,
                              void* d_out, int out_size) {
    const float* z   = (const float*)d_in[0];   // [16,64,64,128] fp32
    const float* emb = (const float*)d_in[1];   // [4096,128] fp32
    float* out = (float*)d_out;

    cudaFuncSetAttribute(argmin_kernel, cudaFuncAttributeMaxDynamicSharedMemorySize,
                         SMEM_BYTES);

    enorm_kernel<<<128, 256>>>(emb);
    argmin_kernel<<<NROWS / BM, 256, SMEM_BYTES>>>(z, emb);
    gather_kernel<<<dim3(HW / 256, DDIM, BATCH), 256>>>(emb, out);
    if (out_size > NELEM) loss_kernel<<<1, 1>>>(out);
}

// round 4
// speedup vs baseline: 1.0016x; 1.0016x over previous
#include <cuda_runtime.h>
#include <cstdint>

// Problem constants
#define NROWS 65536      // B*H*W = 16*64*64
#define DDIM  128
#define KCODE 4096
#define BM    64         // rows per block
#define BK    64         // codes per tile
#define NTILES (KCODE / BK)
#define HW    4096
#define BATCH 16
#define NELEM (16 * 128 * 64 * 64)   // 8388608

// Scratch (no allocations allowed)
__device__ float  g_enorm[KCODE];
__device__ int    g_idx[NROWS];
__device__ double g_loss;

// ---------------------------------------------------------------------------
// Kernel 0: per-code squared norms + zero the loss accumulator
// ---------------------------------------------------------------------------
__global__ void enorm_kernel(const float* __restrict__ emb) {
    if (blockIdx.x == 0 && threadIdx.x == 0) g_loss = 0.0;
    int warp = (blockIdx.x * blockDim.x + threadIdx.x) >> 5;
    int lane = threadIdx.x & 31;
    int nwarps = (gridDim.x * blockDim.x) >> 5;
    for (int k = warp; k < KCODE; k += nwarps) {
        const float4* row = reinterpret_cast<const float4*>(emb + (size_t)k * DDIM);
        float4 v = row[lane];   // 32 lanes * 4 = 128 dims
        float s = v.x * v.x + v.y * v.y + v.z * v.z + v.w * v.w;
        #pragma unroll
        for (int o = 16; o > 0; o >>= 1) s += __shfl_down_sync(0xffffffffu, s, o);
        if (lane == 0) g_enorm[k] = s;
    }
}

// ---------------------------------------------------------------------------
// Kernel 1: streaming argmin GEMM.
//   score(n,k) = ||e_k||^2 - 2 * z_n . e_k      (||z||^2 constant per row)
//   g_idx[n] = argmin_k score, g_loss += sum_n (||z_n||^2 + min score)
//
// smem layout (dynamic, 73984 B):
//   zs  [128][64]  d-major z tile (transposed once per block)
//   es  [128][64]  d-major e tile, XOR-swizzled columns: p = c ^ ((d>>2 & 15)<<2)
//   z2s [64]       per-row ||z||^2
//   redv[64][16], redi[64][16]  cross-thread min reduction
// ---------------------------------------------------------------------------
#define SMEM_BYTES ((DDIM*BM + DDIM*BK + BM + BM*16) * 4 + BM*16 * 4)

__global__ void __launch_bounds__(256) argmin_kernel(const float* __restrict__ z,
                                                     const float* __restrict__ emb) {
    extern __shared__ float smem[];
    float* zs  = smem;                 // 8192 floats
    float* es  = zs + DDIM * BM;       // 8192 floats
    float* z2s = es + DDIM * BK;       // 64
    float* redv = z2s + BM;            // 1024
    int*   redi = (int*)(redv + BM * 16);

    const int tid = threadIdx.x;
    const int tx = tid & 15;           // code group
    const int ty = tid >> 4;           // row group
    const int row0 = blockIdx.x * BM;

    // ---- load z tile, transpose to d-major (store conflicts irrelevant: once) ----
    const float4* zv = reinterpret_cast<const float4*>(z + (size_t)row0 * DDIM);
    #pragma unroll
    for (int i = 0; i < 8; ++i) {
        int f = i * 256 + tid;
        int r = f >> 5;          // 0..63
        int dc = f & 31;         // float4 chunk along D
        float4 v = zv[r * 32 + dc];
        zs[(dc * 4 + 0) * BM + r] = v.x;
        zs[(dc * 4 + 1) * BM + r] = v.y;
        zs[(dc * 4 + 2) * BM + r] = v.z;
        zs[(dc * 4 + 3) * BM + r] = v.w;
    }
    __syncthreads();

    // per-row ||z||^2 (only needed for the loss)
    if (tid < BM) {
        float s = 0.f;
        #pragma unroll 8
        for (int d = 0; d < DDIM; ++d) { float v = zs[d * BM + tid]; s += v * v; }
        z2s[tid] = s;
    }

    float bestv[4];
    int   besti[4];
    #pragma unroll
    for (int i = 0; i < 4; ++i) { bestv[i] = 3.4e38f; besti[i] = 0; }

    for (int kt = 0; kt < NTILES; ++kt) {
        // ---- load e tile, transpose + swizzle ----
        const float4* ev = reinterpret_cast<const float4*>(emb + (size_t)kt * BK * DDIM);
        #pragma unroll
        for (int i = 0; i < 8; ++i) {
            int f = i * 256 + tid;
            int c = f >> 5;      // code within tile
            int dc = f & 31;
            float4 v = ev[c * 32 + dc];
            int pc = c ^ ((dc & 15) << 2);   // swizzle (pure column permutation per d-group)
            es[(dc * 4 + 0) * BK + pc] = v.x;
            es[(dc * 4 + 1) * BK + pc] = v.y;
            es[(dc * 4 + 2) * BK + pc] = v.z;
            es[(dc * 4 + 3) * BK + pc] = v.w;
        }
        __syncthreads();

        // ---- 4x4 register tile dot products over 128 dims ----
        float acc[4][4];
        #pragma unroll
        for (int i = 0; i < 4; ++i)
            #pragma unroll
            for (int j = 0; j < 4; ++j) acc[i][j] = 0.f;

        #pragma unroll 4
        for (int d4 = 0; d4 < 32; ++d4) {
            // physical column holding logical codes [4*tx .. 4*tx+3] for rows d4*4..d4*4+3
            const int pcol = 4 * (tx ^ (d4 & 15));
            #pragma unroll
            for (int q = 0; q < 4; ++q) {
                const int d = d4 * 4 + q;
                float4 zr = *reinterpret_cast<const float4*>(&zs[d * BM + ty * 4]);
                float4 ec = *reinterpret_cast<const float4*>(&es[d * BK + pcol]);
                acc[0][0] += zr.x * ec.x; acc[0][1] += zr.x * ec.y;
                acc[0][2] += zr.x * ec.z; acc[0][3] += zr.x * ec.w;
                acc[1][0] += zr.y * ec.x; acc[1][1] += zr.y * ec.y;
                acc[1][2] += zr.y * ec.z; acc[1][3] += zr.y * ec.w;
                acc[2][0] += zr.z * ec.x; acc[2][1] += zr.z * ec.y;
                acc[2][2] += zr.z * ec.z; acc[2][3] += zr.z * ec.w;
                acc[3][0] += zr.w * ec.x; acc[3][1] += zr.w * ec.y;
                acc[3][2] += zr.w * ec.z; acc[3][3] += zr.w * ec.w;
            }
        }

        // ---- score + running min (k strictly increasing => '<' matches argmin first-min) ----
        #pragma unroll
        for (int j = 0; j < 4; ++j) {
            int cg = kt * BK + tx * 4 + j;
            float en = __ldg(&g_enorm[cg]);
            #pragma unroll
            for (int i = 0; i < 4; ++i) {
                float sc = fmaf(-2.f, acc[i][j], en);
                if (sc < bestv[i]) { bestv[i] = sc; besti[i] = cg; }
            }
        }
        __syncthreads();   // before overwriting es next tile
    }

    // ---- cross-thread (tx) min reduction per row ----
    #pragma unroll
    for (int i = 0; i < 4; ++i) {
        int r = ty * 4 + i;
        redv[r * 16 + tx] = bestv[i];
        redi[r * 16 + tx] = besti[i];
    }
    __syncthreads();

    if (tid < BM) {
        int r = tid;
        float bv = redv[r * 16];
        int   bi = redi[r * 16];
        #pragma unroll
        for (int t = 1; t < 16; ++t) {
            float v = redv[r * 16 + t];
            int  ii = redi[r * 16 + t];
            if (v < bv || (v == bv && ii < bi)) { bv = v; bi = ii; }
        }
        g_idx[row0 + r] = bi;
        double dd = (double)(z2s[r] + bv);   // ||z - e||^2 for this row
        #pragma unroll
        for (int o = 16; o > 0; o >>= 1)
            dd += __shfl_down_sync(0xffffffffu, dd, o);
        if ((tid & 31) == 0) atomicAdd(&g_loss, dd);
    }
}

// ---------------------------------------------------------------------------
// Kernel 2: gather + transpose to [B, D, H, W]. Coalesced stores along hw.
// ---------------------------------------------------------------------------
__global__ void gather_kernel(const float* __restrict__ emb, float* __restrict__ out) {
    int hw = blockIdx.x * blockDim.x + threadIdx.x;  // 0..4095
    int d  = blockIdx.y;                             // 0..127
    int b  = blockIdx.z;                             // 0..15
    int id = g_idx[b * HW + hw];
    out[((size_t)(b * DDIM + d)) * HW + hw] = __ldg(&emb[(size_t)id * DDIM + d]);
}

// ---------------------------------------------------------------------------
// Kernel 3: scalar loss = 1.25 * mean(||z_q - z||^2)
// ---------------------------------------------------------------------------
__global__ void loss_kernel(float* __restrict__ out) {
    out[NELEM] = (float)(1.25 * g_loss / (double)NELEM);
}

// ---------------------------------------------------------------------------
extern "C" void kernel_launch(void* const* d_in, const int* in_sizes, int n_in,
                              void* d_out, int out_size) {
    const float* z   = (const float*)d_in[0];   // [16,64,64,128] fp32
    const float* emb = (const float*)d_in[1];   // [4096,128] fp32
    float* out = (float*)d_out;

    cudaFuncSetAttribute(argmin_kernel, cudaFuncAttributeMaxDynamicSharedMemorySize,
                         SMEM_BYTES);

    enorm_kernel<<<128, 256>>>(emb);
    argmin_kernel<<<NROWS / BM, 256, SMEM_BYTES>>>(z, emb);
    gather_kernel<<<dim3(HW / 256, DDIM, BATCH), 256>>>(emb, out);
    if (out_size > NELEM) loss_kernel<<<1, 1>>>(out);
}

// round 7
// speedup vs baseline: 2.8716x; 2.8671x over previous
#include <cuda_runtime.h>
#include <cuda_bf16.h>
#include <cstdint>

// ---------------- problem constants ----------------
#define NROWS 65536          // B*H*W
#define DDIM  128
#define KCODE 4096
#define TM    128            // rows per CTA
#define TN    128            // codes per tile
#define NT    (KCODE / TN)   // 32 tiles
#define HW    4096
#define BATCH 16
#define NELEM (BATCH * DDIM * HW)   // 8388608
#define NCAND 48

// ---------------- device scratch (no allocs allowed) ----------------
__device__ uint4  g_zb4[NROWS * 16];     // bf16(-2z), 256B/row  (16 MB)
__device__ uint4  g_eb4[KCODE * 16];     // bf16(e),   256B/row  (1 MB)
__device__ float  g_enorm[KCODE];
__device__ int    g_cand[NROWS * NCAND]; // 12.6 MB
__device__ int    g_idx[NROWS];
__device__ double g_loss;

// ---------------- smem layout ----------------
#define SA    0                 // A tile 128x128 bf16         (32768)
#define SB    32768             // B tiles x2                  (65536)
#define SBIAS 98304             // 4096 f32 ||e||^2            (16384)
#define SMEM_TOT (98304 + 16384 + 1024)

static __device__ __forceinline__ uint32_t smem_u32(const void* p) {
    uint32_t a;
    asm("{ .reg .u64 t; cvta.to.shared.u64 t, %1; cvt.u32.u64 %0, t; }" : "=r"(a) : "l"(p));
    return a;
}
static __device__ __forceinline__ void ldsm4(uint32_t a[4], uint32_t addr) {
    asm volatile("ldmatrix.sync.aligned.m8n8.x4.shared.b16 {%0,%1,%2,%3}, [%4];"
                 : "=r"(a[0]), "=r"(a[1]), "=r"(a[2]), "=r"(a[3]) : "r"(addr));
}
static __device__ __forceinline__ void mma16816(float c[4], const uint32_t a[4],
                                                uint32_t b0, uint32_t b1) {
    asm volatile("mma.sync.aligned.m16n8k16.row.col.f32.bf16.bf16.f32 "
                 "{%0,%1,%2,%3}, {%4,%5,%6,%7}, {%8,%9}, {%0,%1,%2,%3};"
                 : "+f"(c[0]), "+f"(c[1]), "+f"(c[2]), "+f"(c[3])
                 : "r"(a[0]), "r"(a[1]), "r"(a[2]), "r"(a[3]), "r"(b0), "r"(b1));
}
#define CP_ASYNC16(dst, src) \
    asm volatile("cp.async.cg.shared.global [%0], [%1], 16;" :: "r"(dst), "l"(src) : "memory")
#define CP_COMMIT() asm volatile("cp.async.commit_group;" ::: "memory")
#define CP_WAIT(N)  asm volatile("cp.async.wait_group %0;" :: "n"(N) : "memory")

static __device__ __forceinline__ uint32_t bf2(float lo, float hi) {
    uint32_t p;
    asm("cvt.rn.bf16x2.f32 %0, %1, %2;" : "=r"(p) : "f"(hi), "f"(lo));
    return p;
}

// ---------------------------------------------------------------------------
// Kernel 0a: z -> bf16(-2z), packed; also zero loss
// ---------------------------------------------------------------------------
__global__ void zconv_kernel(const float* __restrict__ z) {
    if (blockIdx.x == 0 && threadIdx.x == 0) g_loss = 0.0;
    int i = blockIdx.x * blockDim.x + threadIdx.x;     // < NROWS*DDIM/8 = 1048576
    const float4* z4 = reinterpret_cast<const float4*>(z);
    float4 a = z4[i * 2], b = z4[i * 2 + 1];
    uint4 o;
    o.x = bf2(-2.f * a.x, -2.f * a.y);
    o.y = bf2(-2.f * a.z, -2.f * a.w);
    o.z = bf2(-2.f * b.x, -2.f * b.y);
    o.w = bf2(-2.f * b.z, -2.f * b.w);
    g_zb4[i] = o;
}

// ---------------------------------------------------------------------------
// Kernel 0b: emb -> bf16 + ||e||^2
// ---------------------------------------------------------------------------
__global__ void econv_kernel(const float* __restrict__ emb) {
    int w = (blockIdx.x * blockDim.x + threadIdx.x) >> 5;   // code, grid 512*8 = 4096
    int l = threadIdx.x & 31;
    float4 v = reinterpret_cast<const float4*>(emb)[w * 32 + l];
    float s = v.x * v.x + v.y * v.y + v.z * v.z + v.w * v.w;
    #pragma unroll
    for (int o = 16; o > 0; o >>= 1) s += __shfl_xor_sync(0xffffffffu, s, o);
    if (l == 0) g_enorm[w] = s;
    uint2 p;
    p.x = bf2(v.x, v.y);
    p.y = bf2(v.z, v.w);
    reinterpret_cast<uint2*>(g_eb4)[w * 32 + l] = p;
}

// ---------------------------------------------------------------------------
// Kernel 1: bf16 mma.sync GEMM (-2 z @ e^T), streaming top-3 per code-stream
// ---------------------------------------------------------------------------
#define TOP3(sl, s, c) do {                                                     \
    if ((s) < bv2[sl]) {                                                        \
        if ((s) < bv0[sl]) { bv2[sl]=bv1[sl]; bi2[sl]=bi1[sl];                  \
                             bv1[sl]=bv0[sl]; bi1[sl]=bi0[sl];                  \
                             bv0[sl]=(s);     bi0[sl]=(c); }                    \
        else if ((s) < bv1[sl]) { bv2[sl]=bv1[sl]; bi2[sl]=bi1[sl];             \
                                  bv1[sl]=(s);     bi1[sl]=(c); }               \
        else { bv2[sl]=(s); bi2[sl]=(c); }                                      \
    } } while (0)

__global__ void __launch_bounds__(256, 1) vq_mma_kernel() {
    extern __shared__ char smraw[];
    uint32_t sb0 = smem_u32(smraw);
    uint32_t base = (sb0 + 1023u) & ~1023u;
    char* sm = smraw + (base - sb0);

    const int tid = threadIdx.x;
    const int wid = tid >> 5;
    const int l   = tid & 31;
    const int wm  = wid >> 2;      // 0..1 (M)
    const int wn  = wid & 3;       // 0..3 (N)
    const int row0 = blockIdx.x * TM;

    // bias copy (4096 f32)
    for (int i = tid; i < 1024; i += 256)
        reinterpret_cast<float4*>(sm + SBIAS)[i] =
            reinterpret_cast<const float4*>(g_enorm)[i];

    // ---- A tile (z rows), swizzled: chunk' = c ^ (r&7) ----
    {
        const char* srcb = reinterpret_cast<const char*>(g_zb4) + (size_t)row0 * 256;
        #pragma unroll
        for (int i = 0; i < 8; ++i) {
            int f = i * 256 + tid;
            int r = f >> 4, c = f & 15;
            uint32_t dst = base + SA + r * 256 + ((c ^ (r & 7)) << 4);
            CP_ASYNC16(dst, srcb + r * 256 + c * 16);
        }
    }
    // ---- B tile 0 ----
    {
        const char* srcb = reinterpret_cast<const char*>(g_eb4);
        #pragma unroll
        for (int i = 0; i < 8; ++i) {
            int f = i * 256 + tid;
            int r = f >> 4, c = f & 15;
            uint32_t dst = base + SB + r * 256 + ((c ^ (r & 7)) << 4);
            CP_ASYNC16(dst, srcb + r * 256 + c * 16);
        }
    }
    CP_COMMIT();

    // ---- fragment address precompute ----
    uint32_t aab[4], bab[2];
    {
        int arow_l = ((l >> 3) & 1) * 8 + (l & 7);
        #pragma unroll
        for (int mf = 0; mf < 4; ++mf)
            aab[mf] = base + SA + (wm * 64 + mf * 16 + arow_l) * 256;
        int brow_l = ((l >> 4) & 1) * 8 + (l & 7);
        #pragma unroll
        for (int np = 0; np < 2; ++np)
            bab[np] = (wn * 32 + np * 16 + brow_l) * 256;
    }
    const int asel = (l >> 4) & 1;
    const int bsel = (l >> 3) & 1;
    const int sw   = l & 7;

    float bv0[8], bv1[8], bv2[8];
    int   bi0[8], bi1[8], bi2[8];
    #pragma unroll
    for (int s = 0; s < 8; ++s) {
        bv0[s] = bv1[s] = bv2[s] = 3.4e38f;
        bi0[s] = bi1[s] = bi2[s] = 0;
    }

    for (int kt = 0; kt < NT; ++kt) {
        __syncthreads();   // all warps done with buffer being overwritten
        if (kt + 1 < NT) {
            const char* srcb = reinterpret_cast<const char*>(g_eb4) +
                               (size_t)(kt + 1) * TN * 256;
            uint32_t dstb = base + SB + ((kt + 1) & 1) * 32768;
            #pragma unroll
            for (int i = 0; i < 8; ++i) {
                int f = i * 256 + tid;
                int r = f >> 4, c = f & 15;
                CP_ASYNC16(dstb + r * 256 + ((c ^ (r & 7)) << 4), srcb + r * 256 + c * 16);
            }
            CP_COMMIT();
            CP_WAIT(1);
        } else {
            CP_WAIT(0);
        }
        __syncthreads();   // B(kt) (and A at kt=0) visible

        const uint32_t bufb = base + SB + (kt & 1) * 32768;

        float acc[4][4][4];
        #pragma unroll
        for (int mf = 0; mf < 4; ++mf)
            #pragma unroll
            for (int nf = 0; nf < 4; ++nf)
                #pragma unroll
                for (int q = 0; q < 4; ++q) acc[mf][nf][q] = 0.f;

        #pragma unroll
        for (int ks = 0; ks < 8; ++ks) {
            const int c2 = 2 * ks;
            uint32_t Af[4][4], Bf[2][4];
            const uint32_t aoff = (uint32_t)((c2 + asel) ^ sw) << 4;
            const uint32_t boff = (uint32_t)((c2 + bsel) ^ sw) << 4;
            #pragma unroll
            for (int mf = 0; mf < 4; ++mf) ldsm4(Af[mf], aab[mf] + aoff);
            #pragma unroll
            for (int np = 0; np < 2; ++np) ldsm4(Bf[np], bufb + bab[np] + boff);
            #pragma unroll
            for (int mf = 0; mf < 4; ++mf) {
                #pragma unroll
                for (int nf = 0; nf < 4; ++nf) {
                    const int np = nf >> 1, hi = (nf & 1) * 2;
                    mma16816(acc[mf][nf], Af[mf], Bf[np][hi], Bf[np][hi + 1]);
                }
            }
        }

        // ---- epilogue: score + top-3 ----
        const float* biasrow = reinterpret_cast<const float*>(sm + SBIAS) + kt * 128 + wn * 32;
        #pragma unroll
        for (int nf = 0; nf < 4; ++nf) {
            const int cb = nf * 8 + 2 * (l & 3);
            const float2 bp = *reinterpret_cast<const float2*>(biasrow + cb);
            const int cidx = kt * 128 + wn * 32 + cb;
            #pragma unroll
            for (int mf = 0; mf < 4; ++mf) {
                float s0 = acc[mf][nf][0] + bp.x;
                float s1 = acc[mf][nf][1] + bp.y;
                float s2 = acc[mf][nf][2] + bp.x;
                float s3 = acc[mf][nf][3] + bp.y;
                TOP3(mf * 2,     s0, cidx);
                TOP3(mf * 2,     s1, cidx + 1);
                TOP3(mf * 2 + 1, s2, cidx);
                TOP3(mf * 2 + 1, s3, cidx + 1);
            }
        }
    }

    // ---- candidate writeout: 16 thread-positions x 3 per row ----
    #pragma unroll
    for (int s = 0; s < 8; ++s) {
        int row = row0 + wm * 64 + (s >> 1) * 16 + (s & 1) * 8 + (l >> 2);
        int p = wn * 4 + (l & 3);
        int* d = g_cand + (size_t)row * NCAND + p * 3;
        d[0] = bi0[s]; d[1] = bi1[s]; d[2] = bi2[s];
    }
}

// ---------------------------------------------------------------------------
// Kernel 2: exact fp32 rescore of 48 candidates/row -> g_idx + loss
// ---------------------------------------------------------------------------
__global__ void __launch_bounds__(256) rescore_kernel(const float* __restrict__ z,
                                                      const float* __restrict__ emb) {
    __shared__ double wloss[8];
    const int w = threadIdx.x >> 5;
    const int l = threadIdx.x & 31;
    const int r = blockIdx.x * 8 + w;

    float4 zv = reinterpret_cast<const float4*>(z)[(size_t)r * 32 + l];
    float zsq = zv.x * zv.x + zv.y * zv.y + zv.z * zv.z + zv.w * zv.w;
    #pragma unroll
    for (int o = 16; o > 0; o >>= 1) zsq += __shfl_xor_sync(0xffffffffu, zsq, o);

    float bestv = 3.4e38f;
    int   besti = 0x7fffffff;
    for (int j = 0; j < NCAND; ++j) {
        int c = g_cand[(size_t)r * NCAND + j];
        float4 ev = reinterpret_cast<const float4*>(emb)[(size_t)c * 32 + l];
        float d = zv.x * ev.x + zv.y * ev.y + zv.z * ev.z + zv.w * ev.w;
        #pragma unroll
        for (int o = 16; o > 0; o >>= 1) d += __shfl_xor_sync(0xffffffffu, d, o);
        float sc = fmaf(-2.f, d, __ldg(&g_enorm[c]));
        if (sc < bestv || (sc == bestv && c < besti)) { bestv = sc; besti = c; }
    }
    if (l == 0) {
        g_idx[r] = besti;
        wloss[w] = (double)(zsq + bestv);
    }
    __syncthreads();
    if (threadIdx.x == 0) {
        double s = 0.0;
        #pragma unroll
        for (int i = 0; i < 8; ++i) s += wloss[i];
        atomicAdd(&g_loss, s);
    }
}

// ---------------------------------------------------------------------------
// Kernel 3: gather + transpose to [B, D, H, W]
// ---------------------------------------------------------------------------
__global__ void gather_kernel(const float* __restrict__ emb, float* __restrict__ out) {
    int hw = blockIdx.x * blockDim.x + threadIdx.x;  // 0..4095
    int d4 = blockIdx.y;                             // 0..31
    int b  = blockIdx.z;                             // 0..15
    int id = g_idx[b * HW + hw];
    float4 e = __ldg(reinterpret_cast<const float4*>(emb) + (size_t)id * 32 + d4);
    size_t ob = ((size_t)b * DDIM + d4 * 4) * HW + hw;
    out[ob]          = e.x;
    out[ob + HW]     = e.y;
    out[ob + 2 * HW] = e.z;
    out[ob + 3 * HW] = e.w;
}

// ---------------------------------------------------------------------------
// Kernel 4: scalar loss = 1.25 * mean(||z_q - z||^2)
// ---------------------------------------------------------------------------
__global__ void loss_kernel(float* __restrict__ out) {
    out[NELEM] = (float)(1.25 * g_loss / (double)NELEM);
}

// ---------------------------------------------------------------------------
extern "C" void kernel_launch(void* const* d_in, const int* in_sizes, int n_in,
                              void* d_out, int out_size) {
    const float* z   = (const float*)d_in[0];   // [16,64,64,128] fp32
    const float* emb = (const float*)d_in[1];   // [4096,128] fp32
    float* out = (float*)d_out;

    cudaFuncSetAttribute(vq_mma_kernel, cudaFuncAttributeMaxDynamicSharedMemorySize,
                         SMEM_TOT);

    zconv_kernel<<<4096, 256>>>(z);
    econv_kernel<<<512, 256>>>(emb);
    vq_mma_kernel<<<NROWS / TM, 256, SMEM_TOT>>>();
    rescore_kernel<<<NROWS / 8, 256>>>(z, emb);
    gather_kernel<<<dim3(HW / 256, DDIM / 4, BATCH), 256>>>(emb, out);
    if (out_size > NELEM) loss_kernel<<<1, 1>>>(out);
}

// round 9
// speedup vs baseline: 3.6443x; 1.2691x over previous
#include <cuda_runtime.h>
#include <cuda_bf16.h>
#include <cstdint>

// ---------------- problem constants ----------------
#define NROWS 65536          // B*H*W
#define DDIM  128
#define KCODE 4096
#define TM    128            // rows per CTA
#define TN    128            // codes per tile
#define NT    (KCODE / TN)   // 32 tiles
#define HW    4096
#define BATCH 16
#define NELEM (BATCH * DDIM * HW)   // 8388608
#define NCAND 96             // 32 streams x top-3
#define EPSF  0.5f

// ---------------- device scratch (no allocs allowed) ----------------
__device__ uint4  g_zb4[NROWS * 16];      // bf16(-2z), 256B/row
__device__ uint4  g_eb4[KCODE * 16];      // bf16(e),   256B/row
__device__ float  g_enorm[KCODE];
__device__ int    g_cand[NROWS * NCAND];
__device__ float  g_candv[NROWS * NCAND];
__device__ int    g_idx[NROWS];
__device__ double g_loss;

// ---------------- smem layout ----------------
#define SA    0                 // A tile 128x128 bf16  (32768)
#define SB    32768             // B tiles x2           (65536)
#define SMEM_TOT (32768 + 65536 + 1024)

static __device__ __forceinline__ uint32_t smem_u32(const void* p) {
    uint32_t a;
    asm("{ .reg .u64 t; cvta.to.shared.u64 t, %1; cvt.u32.u64 %0, t; }" : "=r"(a) : "l"(p));
    return a;
}
static __device__ __forceinline__ void ldsm4(uint32_t a[4], uint32_t addr) {
    asm volatile("ldmatrix.sync.aligned.m8n8.x4.shared.b16 {%0,%1,%2,%3}, [%4];"
                 : "=r"(a[0]), "=r"(a[1]), "=r"(a[2]), "=r"(a[3]) : "r"(addr));
}
static __device__ __forceinline__ void mma16816(float c[4], const uint32_t a[4],
                                                uint32_t b0, uint32_t b1) {
    asm volatile("mma.sync.aligned.m16n8k16.row.col.f32.bf16.bf16.f32 "
                 "{%0,%1,%2,%3}, {%4,%5,%6,%7}, {%8,%9}, {%0,%1,%2,%3};"
                 : "+f"(c[0]), "+f"(c[1]), "+f"(c[2]), "+f"(c[3])
                 : "r"(a[0]), "r"(a[1]), "r"(a[2]), "r"(a[3]), "r"(b0), "r"(b1));
}
#define CP_ASYNC16(dst, src) \
    asm volatile("cp.async.cg.shared.global [%0], [%1], 16;" :: "r"(dst), "l"(src) : "memory")
#define CP_COMMIT() asm volatile("cp.async.commit_group;" ::: "memory")
#define CP_WAIT(N)  asm volatile("cp.async.wait_group %0;" :: "n"(N) : "memory")

static __device__ __forceinline__ uint32_t bf2(float lo, float hi) {
    uint32_t p;
    asm("cvt.rn.bf16x2.f32 %0, %1, %2;" : "=r"(p) : "f"(hi), "f"(lo));
    return p;
}

// ---------------------------------------------------------------------------
// Kernel 0a: z -> bf16(-2z); zero loss
// ---------------------------------------------------------------------------
__global__ void zconv_kernel(const float* __restrict__ z) {
    if (blockIdx.x == 0 && threadIdx.x == 0) g_loss = 0.0;
    int i = blockIdx.x * blockDim.x + threadIdx.x;     // < 1048576
    const float4* z4 = reinterpret_cast<const float4*>(z);
    float4 a = z4[i * 2], b = z4[i * 2 + 1];
    uint4 o;
    o.x = bf2(-2.f * a.x, -2.f * a.y);
    o.y = bf2(-2.f * a.z, -2.f * a.w);
    o.z = bf2(-2.f * b.x, -2.f * b.y);
    o.w = bf2(-2.f * b.z, -2.f * b.w);
    g_zb4[i] = o;
}

// ---------------------------------------------------------------------------
// Kernel 0b: emb -> bf16 + ||e||^2
// ---------------------------------------------------------------------------
__global__ void econv_kernel(const float* __restrict__ emb) {
    int w = (blockIdx.x * blockDim.x + threadIdx.x) >> 5;   // code
    int l = threadIdx.x & 31;
    float4 v = reinterpret_cast<const float4*>(emb)[w * 32 + l];
    float s = v.x * v.x + v.y * v.y + v.z * v.z + v.w * v.w;
    #pragma unroll
    for (int o = 16; o > 0; o >>= 1) s += __shfl_xor_sync(0xffffffffu, s, o);
    if (l == 0) g_enorm[w] = s;
    uint2 p;
    p.x = bf2(v.x, v.y);
    p.y = bf2(v.z, v.w);
    reinterpret_cast<uint2*>(g_eb4)[w * 32 + l] = p;
}

// ---------------------------------------------------------------------------
// Kernel 1: bf16 mma.sync GEMM, 512 threads, warp tile 64x16, top-3/stream
// ---------------------------------------------------------------------------
#define TOP3(sl, s, c) do {                                                     \
    if ((s) < bv2[sl]) {                                                        \
        if ((s) < bv0[sl]) { bv2[sl]=bv1[sl]; bi2[sl]=bi1[sl];                  \
                             bv1[sl]=bv0[sl]; bi1[sl]=bi0[sl];                  \
                             bv0[sl]=(s);     bi0[sl]=(c); }                    \
        else if ((s) < bv1[sl]) { bv2[sl]=bv1[sl]; bi2[sl]=bi1[sl];             \
                                  bv1[sl]=(s);     bi1[sl]=(c); }               \
        else { bv2[sl]=(s); bi2[sl]=(c); }                                      \
    } } while (0)

__global__ void __launch_bounds__(512, 1) vq_mma_kernel() {
    extern __shared__ char smraw[];
    uint32_t sb0 = smem_u32(smraw);
    uint32_t base = (sb0 + 1023u) & ~1023u;

    const int tid = threadIdx.x;
    const int wid = tid >> 5;
    const int l   = tid & 31;
    const int wm  = wid >> 3;      // 0..1 : 64-row group
    const int wn  = wid & 7;       // 0..7 : 16-code column
    const int row0 = blockIdx.x * TM;

    // ---- A tile (z rows, bf16(-2z)) + B tile 0, swizzle chunk' = c ^ (r&7) ----
    {
        const char* srcA = reinterpret_cast<const char*>(g_zb4) + (size_t)row0 * 256;
        const char* srcB = reinterpret_cast<const char*>(g_eb4);
        #pragma unroll
        for (int i = 0; i < 4; ++i) {
            int f = i * 512 + tid;
            int r = f >> 4, c = f & 15;
            uint32_t so = r * 256 + ((c ^ (r & 7)) << 4);
            CP_ASYNC16(base + SA + so, srcA + r * 256 + c * 16);
            CP_ASYNC16(base + SB + so, srcB + r * 256 + c * 16);
        }
    }
    CP_COMMIT();

    // ---- fragment addresses ----
    uint32_t aab[4], bab;
    {
        int arow_l = ((l >> 3) & 1) * 8 + (l & 7);
        #pragma unroll
        for (int mf = 0; mf < 4; ++mf)
            aab[mf] = base + SA + (wm * 64 + mf * 16 + arow_l) * 256;
        int brow_l = ((l >> 4) & 1) * 8 + (l & 7);
        bab = (wn * 16 + brow_l) * 256;
    }
    const int asel = (l >> 4) & 1;
    const int bsel = (l >> 3) & 1;
    const int sw   = l & 7;

    float bv0[8], bv1[8], bv2[8];
    int   bi0[8], bi1[8], bi2[8];
    #pragma unroll
    for (int s = 0; s < 8; ++s) {
        bv0[s] = bv1[s] = bv2[s] = 3.4e38f;
        bi0[s] = bi1[s] = bi2[s] = 0;
    }

    for (int kt = 0; kt < NT; ++kt) {
        __syncthreads();   // everyone done reading the buffer being overwritten
        if (kt + 1 < NT) {
            const char* srcb = reinterpret_cast<const char*>(g_eb4) +
                               (size_t)(kt + 1) * TN * 256;
            uint32_t dstb = base + SB + ((kt + 1) & 1) * 32768;
            #pragma unroll
            for (int i = 0; i < 4; ++i) {
                int f = i * 512 + tid;
                int r = f >> 4, c = f & 15;
                CP_ASYNC16(dstb + r * 256 + ((c ^ (r & 7)) << 4), srcb + r * 256 + c * 16);
            }
            CP_COMMIT();
            CP_WAIT(1);
        } else {
            CP_WAIT(0);
        }
        __syncthreads();   // B(kt) (and A at kt=0) visible

        const uint32_t bufb = base + SB + (kt & 1) * 32768;

        float acc[4][2][4];
        #pragma unroll
        for (int mf = 0; mf < 4; ++mf)
            #pragma unroll
            for (int nf = 0; nf < 2; ++nf)
                #pragma unroll
                for (int q = 0; q < 4; ++q) acc[mf][nf][q] = 0.f;

        #pragma unroll
        for (int ks = 0; ks < 8; ++ks) {
            const int c2 = 2 * ks;
            uint32_t Af[4][4], Bf[4];
            const uint32_t aoff = (uint32_t)((c2 + asel) ^ sw) << 4;
            const uint32_t boff = (uint32_t)((c2 + bsel) ^ sw) << 4;
            #pragma unroll
            for (int mf = 0; mf < 4; ++mf) ldsm4(Af[mf], aab[mf] + aoff);
            ldsm4(Bf, bufb + bab + boff);
            #pragma unroll
            for (int mf = 0; mf < 4; ++mf) {
                mma16816(acc[mf][0], Af[mf], Bf[0], Bf[1]);
                mma16816(acc[mf][1], Af[mf], Bf[2], Bf[3]);
            }
        }

        // ---- epilogue: score + top-3 (bias via L1-cached ldg) ----
        #pragma unroll
        for (int nf = 0; nf < 2; ++nf) {
            const int cidx = kt * 128 + wn * 16 + nf * 8 + 2 * (l & 3);
            const float2 bp = __ldg(reinterpret_cast<const float2*>(g_enorm + cidx));
            #pragma unroll
            for (int mf = 0; mf < 4; ++mf) {
                float s0 = acc[mf][nf][0] + bp.x;
                float s1 = acc[mf][nf][1] + bp.y;
                float s2 = acc[mf][nf][2] + bp.x;
                float s3 = acc[mf][nf][3] + bp.y;
                TOP3(mf * 2,     s0, cidx);
                TOP3(mf * 2,     s1, cidx + 1);
                TOP3(mf * 2 + 1, s2, cidx);
                TOP3(mf * 2 + 1, s3, cidx + 1);
            }
        }
    }

    // ---- candidate writeout: 32 stream-positions x 3 per row ----
    #pragma unroll
    for (int s = 0; s < 8; ++s) {
        int row = row0 + wm * 64 + (s >> 1) * 16 + (s & 1) * 8 + (l >> 2);
        int p = wn * 4 + (l & 3);
        int*   d  = g_cand  + (size_t)row * NCAND + p * 3;
        float* dv = g_candv + (size_t)row * NCAND + p * 3;
        d[0]  = bi0[s]; d[1]  = bi1[s]; d[2]  = bi2[s];
        dv[0] = bv0[s]; dv[1] = bv1[s]; dv[2] = bv2[s];
    }
}

// ---------------------------------------------------------------------------
// Kernel 2: filtered exact rescore (warp per row; ~1 exact dot per row)
// ---------------------------------------------------------------------------
__global__ void __launch_bounds__(256) rescore_kernel(const float* __restrict__ z,
                                                      const float* __restrict__ emb) {
    __shared__ double wloss[8];
    const int w = threadIdx.x >> 5;
    const int l = threadIdx.x & 31;
    const int r = blockIdx.x * 8 + w;

    float4 zv = reinterpret_cast<const float4*>(z)[(size_t)r * 32 + l];
    float zsq = zv.x * zv.x + zv.y * zv.y + zv.z * zv.z + zv.w * zv.w;
    #pragma unroll
    for (int o = 16; o > 0; o >>= 1) zsq += __shfl_xor_sync(0xffffffffu, zsq, o);

    // lane l owns candidate slots l*3 .. l*3+2
    int   c0 = g_cand [(size_t)r * NCAND + l * 3 + 0];
    int   c1 = g_cand [(size_t)r * NCAND + l * 3 + 1];
    int   c2 = g_cand [(size_t)r * NCAND + l * 3 + 2];
    float v0 = g_candv[(size_t)r * NCAND + l * 3 + 0];
    float v1 = g_candv[(size_t)r * NCAND + l * 3 + 1];
    float v2 = g_candv[(size_t)r * NCAND + l * 3 + 2];

    float m = fminf(v0, fminf(v1, v2));
    #pragma unroll
    for (int o = 16; o > 0; o >>= 1) m = fminf(m, __shfl_xor_sync(0xffffffffu, m, o));
    const float thr = m + EPSF;

    float bestv = 3.4e38f;
    int   besti = 0x7fffffff;
    #pragma unroll
    for (int i = 0; i < 3; ++i) {
        int   ci = (i == 0) ? c0 : (i == 1) ? c1 : c2;
        float vi = (i == 0) ? v0 : (i == 1) ? v1 : v2;
        unsigned msk = __ballot_sync(0xffffffffu, vi <= thr);
        while (msk) {
            int b = __ffs(msk) - 1;
            msk &= msk - 1;
            int c = __shfl_sync(0xffffffffu, ci, b);
            float4 ev = reinterpret_cast<const float4*>(emb)[(size_t)c * 32 + l];
            float d = zv.x * ev.x + zv.y * ev.y + zv.z * ev.z + zv.w * ev.w;
            #pragma unroll
            for (int o = 16; o > 0; o >>= 1) d += __shfl_xor_sync(0xffffffffu, d, o);
            float sc = fmaf(-2.f, d, __ldg(&g_enorm[c]));
            if (sc < bestv || (sc == bestv && c < besti)) { bestv = sc; besti = c; }
        }
    }

    if (l == 0) {
        g_idx[r] = besti;
        wloss[w] = (double)(zsq + bestv);
    }
    __syncthreads();
    if (threadIdx.x == 0) {
        double s = 0.0;
        #pragma unroll
        for (int i = 0; i < 8; ++i) s += wloss[i];
        atomicAdd(&g_loss, s);
    }
}

// ---------------------------------------------------------------------------
// Kernel 3: gather + transpose to [B, D, H, W]
// ---------------------------------------------------------------------------
__global__ void gather_kernel(const float* __restrict__ emb, float* __restrict__ out) {
    int hw = blockIdx.x * blockDim.x + threadIdx.x;  // 0..4095
    int d4 = blockIdx.y;                             // 0..31
    int b  = blockIdx.z;                             // 0..15
    int id = g_idx[b * HW + hw];
    float4 e = __ldg(reinterpret_cast<const float4*>(emb) + (size_t)id * 32 + d4);
    size_t ob = ((size_t)b * DDIM + d4 * 4) * HW + hw;
    out[ob]          = e.x;
    out[ob + HW]     = e.y;
    out[ob + 2 * HW] = e.z;
    out[ob + 3 * HW] = e.w;
}

// ---------------------------------------------------------------------------
// Kernel 4: scalar loss = 1.25 * mean(||z_q - z||^2)
// ---------------------------------------------------------------------------
__global__ void loss_kernel(float* __restrict__ out) {
    out[NELEM] = (float)(1.25 * g_loss / (double)NELEM);
}

// ---------------------------------------------------------------------------
extern "C" void kernel_launch(void* const* d_in, const int* in_sizes, int n_in,
                              void* d_out, int out_size) {
    const float* z   = (const float*)d_in[0];   // [16,64,64,128] fp32
    const float* emb = (const float*)d_in[1];   // [4096,128] fp32
    float* out = (float*)d_out;

    cudaFuncSetAttribute(vq_mma_kernel, cudaFuncAttributeMaxDynamicSharedMemorySize,
                         SMEM_TOT);

    zconv_kernel<<<4096, 256>>>(z);
    econv_kernel<<<512, 256>>>(emb);
    vq_mma_kernel<<<NROWS / TM, 512, SMEM_TOT>>>();
    rescore_kernel<<<NROWS / 8, 256>>>(z, emb);
    gather_kernel<<<dim3(HW / 256, DDIM / 4, BATCH), 256>>>(emb, out);
    if (out_size > NELEM) loss_kernel<<<1, 1>>>(out);
}